// round 8
// baseline (speedup 1.0000x reference)
#include <cuda_runtime.h>
#include <cuda_bf16.h>
#include <cuda_fp16.h>
#include <cstdint>

#define NTOK 8192
#define DIN  1024
#define DH   128
#define NSPLIT 2
#define KEYS_PER_SPLIT (NTOK / NSPLIT)

// Pre-split inputs (prep kernels).
__device__ __nv_bfloat16 g_Xhi[NTOK * DIN], g_Xlo[NTOK * DIN];
__device__ __nv_bfloat16 g_Whi[3 * DIN * DH], g_Wlo[3 * DIN * DH];
// Split operands produced by the projection kernel.
__device__ __nv_bfloat16 g_Qhi[NTOK * DH], g_Qlo[NTOK * DH]; // pre-scaled by (1/sqrt d)*log2 e
__device__ __nv_bfloat16 g_Khi[NTOK * DH], g_Klo[NTOK * DH];
__device__ __half        g_Vhi[NTOK * DH];
// Split-KV partials.
__device__ float g_Opart[NSPLIT * NTOK * DH];
__device__ float g_Mpart[NSPLIT * NTOK];
__device__ float g_Lpart[NSPLIT * NTOK];

__device__ __forceinline__ uint32_t smem_u32(const void* p) {
  uint32_t a;
  asm("{ .reg .u64 t; cvta.to.shared.u64 t, %1; cvt.u32.u64 %0, t; }"
      : "=r"(a) : "l"(p));
  return a;
}
__device__ __forceinline__ float ex2f(float x) {
  float y; asm("ex2.approx.ftz.f32 %0, %1;" : "=f"(y) : "f"(x)); return y;
}
__device__ __forceinline__ void ldsm4(uint32_t* r, uint32_t addr) {
  asm volatile("ldmatrix.sync.aligned.m8n8.x4.shared.b16 {%0,%1,%2,%3}, [%4];"
               : "=r"(r[0]), "=r"(r[1]), "=r"(r[2]), "=r"(r[3]) : "r"(addr));
}
__device__ __forceinline__ void ldsm4t(uint32_t* r, uint32_t addr) {
  asm volatile("ldmatrix.sync.aligned.m8n8.x4.trans.shared.b16 {%0,%1,%2,%3}, [%4];"
               : "=r"(r[0]), "=r"(r[1]), "=r"(r[2]), "=r"(r[3]) : "r"(addr));
}
__device__ __forceinline__ void mma_bf16(float* d, const uint32_t* a,
                                         const uint32_t* b) {
  asm volatile(
      "mma.sync.aligned.m16n8k16.row.col.f32.bf16.bf16.f32 "
      "{%0,%1,%2,%3}, {%4,%5,%6,%7}, {%8,%9}, {%0,%1,%2,%3};"
      : "+f"(d[0]), "+f"(d[1]), "+f"(d[2]), "+f"(d[3])
      : "r"(a[0]), "r"(a[1]), "r"(a[2]), "r"(a[3]), "r"(b[0]), "r"(b[1]));
}
__device__ __forceinline__ void mma_f16(float* d, const uint32_t* a,
                                        const uint32_t* b) {
  asm volatile(
      "mma.sync.aligned.m16n8k16.row.col.f32.f16.f16.f32 "
      "{%0,%1,%2,%3}, {%4,%5,%6,%7}, {%8,%9}, {%0,%1,%2,%3};"
      : "+f"(d[0]), "+f"(d[1]), "+f"(d[2]), "+f"(d[3])
      : "r"(a[0]), "r"(a[1]), "r"(a[2]), "r"(a[3]), "r"(b[0]), "r"(b[1]));
}
__device__ __forceinline__ void cpa16(uint32_t dst, const void* src) {
  asm volatile("cp.async.cg.shared.global [%0], [%1], 16;" :: "r"(dst), "l"(src));
}
#define CP_COMMIT() asm volatile("cp.async.commit_group;" ::: "memory")
#define CP_WAIT1() asm volatile("cp.async.wait_group 1;" ::: "memory")
#define CP_WAIT0() asm volatile("cp.async.wait_group 0;" ::: "memory")

// ---------------------------------------------------------------------------
// Prep kernels: split fp32 -> bf16 hi/lo.
// ---------------------------------------------------------------------------
__global__ __launch_bounds__(256) void split_x_kernel(const float* __restrict__ x) {
  size_t i = ((size_t)blockIdx.x * 256 + threadIdx.x) * 4;
  float4 v = *(const float4*)(x + i);
  __nv_bfloat16 h0 = __float2bfloat16_rn(v.x), h1 = __float2bfloat16_rn(v.y);
  __nv_bfloat16 h2 = __float2bfloat16_rn(v.z), h3 = __float2bfloat16_rn(v.w);
  __nv_bfloat162 hh0 = __halves2bfloat162(h0, h1), hh1 = __halves2bfloat162(h2, h3);
  __nv_bfloat162 ll0 = __halves2bfloat162(
      __float2bfloat16_rn(v.x - __bfloat162float(h0)),
      __float2bfloat16_rn(v.y - __bfloat162float(h1)));
  __nv_bfloat162 ll1 = __halves2bfloat162(
      __float2bfloat16_rn(v.z - __bfloat162float(h2)),
      __float2bfloat16_rn(v.w - __bfloat162float(h3)));
  *(uint2*)&g_Xhi[i] = make_uint2(*(uint32_t*)&hh0, *(uint32_t*)&hh1);
  *(uint2*)&g_Xlo[i] = make_uint2(*(uint32_t*)&ll0, *(uint32_t*)&ll1);
}

__global__ __launch_bounds__(256) void split_w_kernel(
    const float* __restrict__ Wq, const float* __restrict__ Wk,
    const float* __restrict__ Wv) {
  const float* W;
  float sc = 1.0f;
  if (blockIdx.y == 0) { W = Wq; sc = 0.08838834764831845f * 1.4426950408889634f; }
  else if (blockIdx.y == 1) W = Wk;
  else W = Wv;
  size_t i = ((size_t)blockIdx.x * 256 + threadIdx.x) * 4;
  float4 v = *(const float4*)(W + i);
  v.x *= sc; v.y *= sc; v.z *= sc; v.w *= sc;
  __nv_bfloat16 h0 = __float2bfloat16_rn(v.x), h1 = __float2bfloat16_rn(v.y);
  __nv_bfloat16 h2 = __float2bfloat16_rn(v.z), h3 = __float2bfloat16_rn(v.w);
  __nv_bfloat162 hh0 = __halves2bfloat162(h0, h1), hh1 = __halves2bfloat162(h2, h3);
  __nv_bfloat162 ll0 = __halves2bfloat162(
      __float2bfloat16_rn(v.x - __bfloat162float(h0)),
      __float2bfloat16_rn(v.y - __bfloat162float(h1)));
  __nv_bfloat162 ll1 = __halves2bfloat162(
      __float2bfloat16_rn(v.z - __bfloat162float(h2)),
      __float2bfloat16_rn(v.w - __bfloat162float(h3)));
  size_t o = (size_t)blockIdx.y * DIN * DH + i;
  *(uint2*)&g_Whi[o] = make_uint2(*(uint32_t*)&hh0, *(uint32_t*)&hh1);
  *(uint2*)&g_Wlo[o] = make_uint2(*(uint32_t*)&ll0, *(uint32_t*)&ll1);
}

// ---------------------------------------------------------------------------
// Kernel 1: QKV projection GEMM, BM=64, 128 threads, 2 CTAs/SM.
// grid = (NTOK/64, 3) = 384 CTAs -> ~1.3 waves on 148 SMs.
// Stage: XHI 0 (64x144=9216), XLO 9216, WHI 18432 (64x272=17408),
// WLO 35840; stage 53248 bytes, two stages.
// ---------------------------------------------------------------------------
#define XROW 144
#define WROW 272
#define PSTAGE 53248
#define SMEM_PROJ (2 * PSTAGE)

__device__ __forceinline__ void proj_issue(int tid, int mb, int y, int k0,
                                           uint32_t dstbase) {
#pragma unroll
  for (int it = 0; it < 8; it++) {              // X: 2 arrays x 512 float4
    int idx = tid + it * 128;
    int arr = idx >> 9, w = idx & 511;
    int r = w >> 3, c = w & 7;
    const __nv_bfloat16* src = (arr ? g_Xlo : g_Xhi) +
                               (size_t)(mb + r) * DIN + k0 + c * 8;
    cpa16(dstbase + arr * 9216 + r * XROW + c * 16, src);
  }
#pragma unroll
  for (int it = 0; it < 16; it++) {             // W: 2 arrays x 1024 float4
    int idx = tid + it * 128;
    int arr = idx >> 10, w = idx & 1023;
    int r = w >> 4, c = w & 15;
    const __nv_bfloat16* src = (arr ? g_Wlo : g_Whi) +
                               (size_t)y * DIN * DH + (size_t)(k0 + r) * DH + c * 8;
    cpa16(dstbase + 18432 + arr * 17408 + r * WROW + c * 16, src);
  }
}

__global__ __launch_bounds__(128, 2) void qkv_proj_mma() {
  extern __shared__ char smc[];
  const int tid = threadIdx.x;
  const int lane = tid & 31, warp = tid >> 5;
  const int wm = warp * 16;
  const int mb = blockIdx.x * 64;
  const int y = blockIdx.y;
  const uint32_t sb = smem_u32(smc);

  float acc[16][4];
#pragma unroll
  for (int f = 0; f < 16; f++)
#pragma unroll
    for (int e = 0; e < 4; e++) acc[f][e] = 0.f;

  const uint32_t ah_addr = sb + (uint32_t)(wm + (lane & 15)) * XROW +
                           (lane >> 4) * 16;
  const uint32_t bh_addr = sb + 18432 +
                           (uint32_t)((lane & 7) + ((lane >> 3) & 1) * 8) * WROW +
                           ((lane >> 4) & 1) * 16;

  proj_issue(tid, mb, y, 0, sb);           CP_COMMIT();
  proj_issue(tid, mb, y, 64, sb + PSTAGE); CP_COMMIT();

  const int NT = DIN / 64;   // 16
  for (int t = 0; t < NT; t++) {
    if (t + 1 < NT) CP_WAIT1(); else CP_WAIT0();
    __syncthreads();
    uint32_t bo = (uint32_t)(t & 1) * PSTAGE;
#pragma unroll
    for (int j = 0; j < 4; j++) {
      uint32_t ah[4], al[4];
      ldsm4(ah, ah_addr + bo + j * 32);
      ldsm4(al, ah_addr + bo + 9216 + j * 32);
#pragma unroll
      for (int f2 = 0; f2 < 8; f2++) {
        uint32_t bh[4], bl[4];
        uint32_t a = bh_addr + bo + (uint32_t)(j * 16) * WROW + f2 * 32;
        ldsm4t(bh, a);
        ldsm4t(bl, a + 17408);
        mma_bf16(acc[2 * f2], ah, bh);
        mma_bf16(acc[2 * f2 + 1], ah, bh + 2);
        mma_bf16(acc[2 * f2], ah, bl);
        mma_bf16(acc[2 * f2 + 1], ah, bl + 2);
        mma_bf16(acc[2 * f2], al, bh);
        mma_bf16(acc[2 * f2 + 1], al, bh + 2);
      }
    }
    __syncthreads();
    if (t + 2 < NT) { proj_issue(tid, mb, y, (t + 2) * 64, sb + bo); }
    CP_COMMIT();
  }

  // Epilogue: emit split operands.
  int r0 = mb + wm + (lane >> 2), r1 = r0 + 8;
  int cb = 2 * (lane & 3);
#pragma unroll
  for (int f = 0; f < 16; f++) {
    int c = 8 * f + cb;
    float v0 = acc[f][0], v1 = acc[f][1], v2 = acc[f][2], v3 = acc[f][3];
    if (y == 2) {
      *(__half2*)&g_Vhi[(size_t)r0 * DH + c] = __floats2half2_rn(v0, v1);
      *(__half2*)&g_Vhi[(size_t)r1 * DH + c] = __floats2half2_rn(v2, v3);
    } else {
      __nv_bfloat16 h0 = __float2bfloat16_rn(v0), h1 = __float2bfloat16_rn(v1);
      __nv_bfloat16 h2 = __float2bfloat16_rn(v2), h3 = __float2bfloat16_rn(v3);
      __nv_bfloat16* hi = y ? g_Khi : g_Qhi;
      __nv_bfloat16* lo = y ? g_Klo : g_Qlo;
      *(__nv_bfloat162*)&hi[(size_t)r0 * DH + c] = __halves2bfloat162(h0, h1);
      *(__nv_bfloat162*)&hi[(size_t)r1 * DH + c] = __halves2bfloat162(h2, h3);
      *(__nv_bfloat162*)&lo[(size_t)r0 * DH + c] = __halves2bfloat162(
          __float2bfloat16_rn(v0 - __bfloat162float(h0)),
          __float2bfloat16_rn(v1 - __bfloat162float(h1)));
      *(__nv_bfloat162*)&lo[(size_t)r1 * DH + c] = __halves2bfloat162(
          __float2bfloat16_rn(v2 - __bfloat162float(h2)),
          __float2bfloat16_rn(v3 - __bfloat162float(h3)));
    }
  }
}

// ---------------------------------------------------------------------------
// Kernel 2: flash attention, BM=112 (7 warps, 224 thr), BN=64, split-KV x2.
// grid = (74, 2) = 148 CTAs -> exactly one wave on all SMs.
// 3-stage cp.async ring + resident Q in smem; fused S(t+1)/softmax+PV(t).
// Stage: KHI 0, KLO 17408, VHI 34816; size 52224; 3 stages = 156672.
// Q: Qhi at QOFF (112x272=30464), Qlo at +30464.  Total 217600 B.
// ---------------------------------------------------------------------------
#define ROWB 272
#define SKLO 17408
#define SVHI 34816
#define FSTAGE 52224
#define BMF 112
#define NBLK 74                      // ceil(8192/112)
#define FTHR 224
#define QOFF (3 * FSTAGE)
#define QLO_OFF (BMF * ROWB)         // 30464
#define SMEM_FLASH (QOFF + 2 * QLO_OFF)
#define FNT (KEYS_PER_SPLIT / 64)    // 64 tiles

__device__ __forceinline__ void flash_issue(int tid, int n0, uint32_t dstbase) {
  for (int idx = tid; idx < 3072; idx += FTHR) {
    int arr = idx >> 10, w = idx & 1023;
    int r = w >> 4, c = w & 15;
    const __nv_bfloat16* srcb;
    if (arr == 0)      srcb = g_Khi;
    else if (arr == 1) srcb = g_Klo;
    else               srcb = (const __nv_bfloat16*)g_Vhi;
    cpa16(dstbase + arr * 17408 + r * ROWB + c * 16,
          srcb + (size_t)(n0 + r) * DH + c * 8);
  }
}

// S = Q K^T for one key tile (Q fragments re-loaded from resident smem).
__device__ __forceinline__ void s_mma_tile(float sf[8][4], uint32_t kbase,
                                           uint32_t qh_addr, uint32_t ql_addr) {
#pragma unroll
  for (int f = 0; f < 8; f++)
#pragma unroll
    for (int e = 0; e < 4; e++) sf[f][e] = 0.f;
#pragma unroll
  for (int j = 0; j < 8; j++) {
    uint32_t qh[4], ql[4];
    ldsm4(qh, qh_addr + j * 32);
    ldsm4(ql, ql_addr + j * 32);
#pragma unroll
    for (int f2 = 0; f2 < 4; f2++) {
      uint32_t bh[4], bl[4];
      uint32_t a = kbase + (uint32_t)(f2 * 16) * ROWB + j * 32;
      ldsm4(bh, a);
      ldsm4(bl, a + SKLO);
      mma_bf16(sf[2 * f2], qh, bh);
      mma_bf16(sf[2 * f2 + 1], qh, bh + 2);
      mma_bf16(sf[2 * f2], qh, bl);
      mma_bf16(sf[2 * f2 + 1], qh, bl + 2);
      mma_bf16(sf[2 * f2], ql, bh);
      mma_bf16(sf[2 * f2 + 1], ql, bh + 2);
    }
  }
}

// Online softmax (base-2 logits) + conditional O rescale + PV accumulate.
__device__ __forceinline__ void softmax_pv(float sf[8][4], float of[16][4],
                                           float& mrow0, float& mrow1,
                                           float& l0, float& l1,
                                           uint32_t vbase) {
  float mx0 = sf[0][0], mx1 = sf[0][2];
#pragma unroll
  for (int f = 0; f < 8; f++) {
    mx0 = fmaxf(mx0, fmaxf(sf[f][0], sf[f][1]));
    mx1 = fmaxf(mx1, fmaxf(sf[f][2], sf[f][3]));
  }
  mx0 = fmaxf(mx0, __shfl_xor_sync(0xffffffffu, mx0, 1));
  mx0 = fmaxf(mx0, __shfl_xor_sync(0xffffffffu, mx0, 2));
  mx1 = fmaxf(mx1, __shfl_xor_sync(0xffffffffu, mx1, 1));
  mx1 = fmaxf(mx1, __shfl_xor_sync(0xffffffffu, mx1, 2));

  float mn0 = fmaxf(mrow0, mx0), mn1 = fmaxf(mrow1, mx1);
  float a0 = ex2f(mrow0 - mn0), a1 = ex2f(mrow1 - mn1);
  mrow0 = mn0; mrow1 = mn1;

  float s0 = 0.f, s1 = 0.f;
#pragma unroll
  for (int f = 0; f < 8; f++) {
    sf[f][0] = ex2f(sf[f][0] - mn0);
    sf[f][1] = ex2f(sf[f][1] - mn0);
    sf[f][2] = ex2f(sf[f][2] - mn1);
    sf[f][3] = ex2f(sf[f][3] - mn1);
    s0 += sf[f][0] + sf[f][1];
    s1 += sf[f][2] + sf[f][3];
  }
  s0 += __shfl_xor_sync(0xffffffffu, s0, 1);
  s0 += __shfl_xor_sync(0xffffffffu, s0, 2);
  s1 += __shfl_xor_sync(0xffffffffu, s1, 1);
  s1 += __shfl_xor_sync(0xffffffffu, s1, 2);
  l0 = l0 * a0 + s0;
  l1 = l1 * a1 + s1;

  if (!__all_sync(0xffffffffu, (__float_as_uint(a0) == 0x3f800000u) &&
                              (__float_as_uint(a1) == 0x3f800000u))) {
#pragma unroll
    for (int f = 0; f < 16; f++) {
      of[f][0] *= a0;  of[f][1] *= a0;
      of[f][2] *= a1;  of[f][3] *= a1;
    }
  }

#pragma unroll
  for (int j2 = 0; j2 < 4; j2++) {
    uint32_t ph[4];
    __half2 h;
    h = __floats2half2_rn(sf[2 * j2][0], sf[2 * j2][1]);         ph[0] = *(uint32_t*)&h;
    h = __floats2half2_rn(sf[2 * j2][2], sf[2 * j2][3]);         ph[1] = *(uint32_t*)&h;
    h = __floats2half2_rn(sf[2 * j2 + 1][0], sf[2 * j2 + 1][1]); ph[2] = *(uint32_t*)&h;
    h = __floats2half2_rn(sf[2 * j2 + 1][2], sf[2 * j2 + 1][3]); ph[3] = *(uint32_t*)&h;
    uint32_t ka = vbase + (uint32_t)(j2 * 16) * ROWB;
#pragma unroll
    for (int f2 = 0; f2 < 8; f2++) {
      uint32_t bv[4];
      ldsm4t(bv, ka + f2 * 32);
      mma_f16(of[2 * f2], ph, bv);
      mma_f16(of[2 * f2 + 1], ph, bv + 2);
    }
  }
}

__global__ __launch_bounds__(FTHR, 1) void flash_mma(int dummy) {
  extern __shared__ char smc[];
  const int tid = threadIdx.x;
  const int lane = tid & 31, warp = tid >> 5;
  const int wm = warp * 16;
  const int mb = blockIdx.x * BMF;
  const int split = blockIdx.y;
  const int nbase = split * KEYS_PER_SPLIT;
  const uint32_t sb = smem_u32(smc);

  // Prefetch tiles 0 and 1.
  flash_issue(tid, nbase, sb);                 CP_COMMIT();   // group 0
  flash_issue(tid, nbase + 64, sb + FSTAGE);   CP_COMMIT();   // group 1

  // Stage Q (row-clamped for the partial last block).
  for (int idx = tid; idx < 2 * BMF * 16; idx += FTHR) {
    int arr = idx >= BMF * 16;
    int w = arr ? idx - BMF * 16 : idx;
    int r = w >> 4, c = w & 15;
    int rr = mb + r; if (rr > NTOK - 1) rr = NTOK - 1;
    size_t g = (size_t)rr * DH + c * 8;
    const __nv_bfloat16* src = arr ? g_Qlo : g_Qhi;
    *(float4*)(smc + QOFF + arr * QLO_OFF + r * ROWB + c * 16) =
        *(const float4*)(src + g);
  }

  const uint32_t qh_addr = sb + QOFF + (uint32_t)(wm + (lane & 15)) * ROWB +
                           (lane >> 4) * 16;
  const uint32_t ql_addr = qh_addr + QLO_OFF;
  const uint32_t kaddr = sb + (uint32_t)((lane & 7) + ((lane >> 4) << 3)) * ROWB +
                         ((lane >> 3) & 1) * 16;
  const uint32_t vaddr = sb + (uint32_t)((lane & 7) + (((lane >> 3) & 1) << 3)) * ROWB +
                         ((lane >> 4) & 1) * 16 + SVHI;

  float of[16][4];
#pragma unroll
  for (int f = 0; f < 16; f++)
#pragma unroll
    for (int e = 0; e < 4; e++) of[f][e] = 0.f;
  float mrow0 = -1e30f, mrow1 = -1e30f, l0 = 0.f, l1 = 0.f;
  float sfA[8][4], sfB[8][4];

  CP_WAIT1();          // group 0 complete (group 1 outstanding)
  __syncthreads();     // Q staged + stage-0 data visible
  s_mma_tile(sfA, kaddr, qh_addr, ql_addr);

#define TILE_BODY(T, CUR, NXT)                                                \
  {                                                                           \
    CP_WAIT0();                                                               \
    __syncthreads();                                                          \
    if ((T) + 2 < FNT) {                                                      \
      flash_issue(tid, nbase + ((T) + 2) * 64,                                \
                  sb + (uint32_t)(((T) + 2) % 3) * FSTAGE);                   \
      CP_COMMIT();                                                            \
    }                                                                         \
    s_mma_tile(NXT, kaddr + (uint32_t)((((T) + 1) % 3)) * FSTAGE,             \
               qh_addr, ql_addr);                                             \
    softmax_pv(CUR, of, mrow0, mrow1, l0, l1,                                 \
               vaddr + (uint32_t)((T) % 3) * FSTAGE);                         \
  }

  for (int tp = 0; tp < (FNT - 2) / 2; tp++) {     // t = 0..61
    TILE_BODY(2 * tp, sfA, sfB);
    TILE_BODY(2 * tp + 1, sfB, sfA);
  }
  TILE_BODY(FNT - 2, sfA, sfB);                    // t = 62 (S(63) -> sfB)
  softmax_pv(sfB, of, mrow0, mrow1, l0, l1,
             vaddr + (uint32_t)((FNT - 1) % 3) * FSTAGE);
#undef TILE_BODY

  // ---- write partials (guarded: last block is partial) ----
  int r0 = lane >> 2, r1 = r0 + 8;
  int cbase = 2 * (lane & 3);
  int m0 = mb + wm + r0, m1 = mb + wm + r1;
  if (m0 < NTOK) {
    size_t orow0 = (size_t)(split * NTOK + m0) * DH;
#pragma unroll
    for (int f = 0; f < 16; f++)
      *(float2*)&g_Opart[orow0 + 8 * f + cbase] = make_float2(of[f][0], of[f][1]);
  }
  if (m1 < NTOK) {
    size_t orow1 = (size_t)(split * NTOK + m1) * DH;
#pragma unroll
    for (int f = 0; f < 16; f++)
      *(float2*)&g_Opart[orow1 + 8 * f + cbase] = make_float2(of[f][2], of[f][3]);
  }
  if ((lane & 3) == 0) {
    if (m0 < NTOK) {
      g_Mpart[split * NTOK + m0] = mrow0;
      g_Lpart[split * NTOK + m0] = l0;
    }
    if (m1 < NTOK) {
      g_Mpart[split * NTOK + m1] = mrow1;
      g_Lpart[split * NTOK + m1] = l1;
    }
  }
}

// ---------------------------------------------------------------------------
// Kernel 3: split-KV merge.
// ---------------------------------------------------------------------------
__global__ __launch_bounds__(256) void merge_kernel(float* __restrict__ out) {
  const int tid = threadIdx.x;
  const int row = blockIdx.x * 8 + (tid >> 5);
  const int c4 = (tid & 31) * 4;

  float ma = g_Mpart[row], la = g_Lpart[row];
  float mb2 = g_Mpart[NTOK + row], lb = g_Lpart[NTOK + row];
  float M = fmaxf(ma, mb2);
  float wa = ex2f(ma - M), wb = ex2f(mb2 - M);
  float inv = 1.0f / (wa * la + wb * lb);

  float4 oa = *(const float4*)&g_Opart[(size_t)row * DH + c4];
  float4 ob = *(const float4*)&g_Opart[(size_t)(NTOK + row) * DH + c4];
  float4 r;
  r.x = (wa * oa.x + wb * ob.x) * inv;
  r.y = (wa * oa.y + wb * ob.y) * inv;
  r.z = (wa * oa.z + wb * ob.z) * inv;
  r.w = (wa * oa.w + wb * ob.w) * inv;
  *(float4*)&out[(size_t)row * DH + c4] = r;
}

// ---------------------------------------------------------------------------
extern "C" void kernel_launch(void* const* d_in, const int* in_sizes, int n_in,
                              void* d_out, int out_size) {
  const float* x  = (const float*)d_in[0];
  const float* Wq = (const float*)d_in[1];
  const float* Wk = (const float*)d_in[2];
  const float* Wv = (const float*)d_in[3];
  float* out = (float*)d_out;

  split_x_kernel<<<NTOK * DIN / 1024, 256>>>(x);
  split_w_kernel<<<dim3(DIN * DH / 1024, 3, 1), 256>>>(Wq, Wk, Wv);

  cudaFuncSetAttribute(qkv_proj_mma, cudaFuncAttributeMaxDynamicSharedMemorySize,
                       SMEM_PROJ);
  qkv_proj_mma<<<dim3(NTOK / 64, 3, 1), 128, SMEM_PROJ>>>();

  cudaFuncSetAttribute(flash_mma, cudaFuncAttributeMaxDynamicSharedMemorySize,
                       SMEM_FLASH);
  flash_mma<<<dim3(NBLK, NSPLIT, 1), FTHR, SMEM_FLASH>>>(0);

  merge_kernel<<<NTOK / 8, 256>>>(out);
}